// round 14
// baseline (speedup 1.0000x reference)
#include <cuda_runtime.h>
#include <cuda_bf16.h>
#include <cuda_fp16.h>
#include <cstdint>

#define B_      8
#define Q_      2048
#define DIM_    256
#define NH      8
#define HD      32
#define DFF     1024
#define LEN_IN_ 13294
#define BQ      (B_*Q_)
#define MV      (B_*LEN_IN_)
#define M_FD    106368            // MV padded to 64

// ---------------- scratch ----------------
__device__ uint32_t g_src_fd[13615104];   // source as bf16 A-fragments (54.5 MB)
__device__ uint32_t g_qp_fd[2097152];     // LN1+pos as A-fragments
__device__ uint32_t g_attnout_fd[2097152];// sampler out as A-fragments
__device__ uint32_t g_yb_fd[2097152];     // LN2 out as A-fragments
__device__ uint32_t g_ffn_fd[8388608];    // FFN hidden as A-fragments (33.5 MB)
__device__ __half   g_valh[MV*DIM_];      // fp16 value (54 MB)
__device__ float    g_offattn[BQ*384];    // [off(256) | attn logits(128)]
__device__ float    g_x[BQ*DIM_];         // residual 1 (row-major fp32)
__device__ uint32_t g_wp[376832];         // packed bf16x2 weights (fragment layout)
__device__ float    g_bcat[384];          // concat bias [boff | battn]

#define WP_WV    0
#define WP_PROJ  32768
#define WP_WOUT  81920
#define WP_W1    114688
#define WP_W2    245760

// ---------------- helpers ----------------
__device__ __forceinline__ uint32_t packbf(float lo, float hi) {
    uint32_t d;
    asm("cvt.rn.bf16x2.f32 %0, %1, %2;" : "=r"(d) : "f"(hi), "f"(lo));
    return d;
}

__device__ __forceinline__ void mma_bf16(float c[4], const uint32_t a[4],
                                         uint32_t b0, uint32_t b1) {
    asm("mma.sync.aligned.m16n8k16.row.col.f32.bf16.bf16.f32 "
        "{%0,%1,%2,%3}, {%4,%5,%6,%7}, {%8,%9}, {%0,%1,%2,%3};"
        : "+f"(c[0]), "+f"(c[1]), "+f"(c[2]), "+f"(c[3])
        : "r"(a[0]), "r"(a[1]), "r"(a[2]), "r"(a[3]), "r"(b0), "r"(b1));
}

// A-fragment word index: ((mblk*K16 + kblk)*32 + lane)*4 + j
//   word j of lane (gid=lane>>2, tig=lane&3) holds bf16 pair
//   A[16*mblk + gid + 8*(j&1)][16*kblk + 2*tig + 8*((j>>1)&1) .. +1]
__device__ __forceinline__ size_t afd_idx(int row, int k, int K16) {
    const int mblk = row >> 4, rin = row & 15;
    const int kblk = k >> 4,  kk  = k & 15;
    const int j    = (rin >> 3) | ((kk >> 3) << 1);
    const int lane = (rin & 7) * 4 + ((kk & 7) >> 1);
    return ((size_t)(mblk * K16 + kblk) << 7) + (lane << 2) + j;
}

// ---------------- LayerNorm (+ optional addend) -> fragment bf16 ----------------
__global__ __launch_bounds__(256) void ln_fd_kernel(
    const float* __restrict__ x, const float* __restrict__ g,
    const float* __restrict__ b, const float* __restrict__ addend,
    uint32_t* __restrict__ outfd)
{
    __shared__ float sbuf[8];
    const int row = blockIdx.x;
    const int t = threadIdx.x;
    const float v = x[(size_t)row*DIM_ + t];

    float s = v;
    #pragma unroll
    for (int o = 16; o; o >>= 1) s += __shfl_xor_sync(0xffffffffu, s, o);
    if ((t & 31) == 0) sbuf[t >> 5] = s;
    __syncthreads();
    float mean = 0.f;
    #pragma unroll
    for (int i = 0; i < 8; i++) mean += sbuf[i];
    mean *= (1.f/256.f);

    const float d = v - mean;
    float s2 = d*d;
    #pragma unroll
    for (int o = 16; o; o >>= 1) s2 += __shfl_xor_sync(0xffffffffu, s2, o);
    __syncthreads();
    if ((t & 31) == 0) sbuf[t >> 5] = s2;
    __syncthreads();
    float var = 0.f;
    #pragma unroll
    for (int i = 0; i < 8; i++) var += sbuf[i];
    var *= (1.f/256.f);

    float r = d * rsqrtf(var + 1e-5f) * g[t] + b[t];
    if (addend) r += addend[(size_t)row*DIM_ + t];

    const float r1 = __shfl_down_sync(0xffffffffu, r, 1);
    if ((t & 1) == 0)
        outfd[afd_idx(row, t, DIM_/16)] = packbf(r, r1);
}

// ---------------- source fp32 row-major -> A fragments ----------------
__global__ __launch_bounds__(256) void src_pack(const float* __restrict__ src,
                                                uint32_t* __restrict__ outfd)
{
    const int gidx = blockIdx.x * 256 + threadIdx.x;   // (row, kpair)
    if (gidx >= M_FD * 128) return;
    const int row = gidx >> 7;
    const int k   = (gidx & 127) << 1;
    float lo = 0.f, hi = 0.f;
    if (row < MV) {
        const float2 v = *(const float2*)(src + (size_t)row*DIM_ + k);
        lo = v.x; hi = v.y;
    }
    outfd[afd_idx(row, k, DIM_/16)] = packbf(lo, hi);
}

// ---------------- single-launch weight pack (B fragment layout, unchanged) ----------------
struct WPackArgs {
    const float *Wv, *Woff, *Wattn, *Wout, *W1, *W2, *boff, *battn;
};

__device__ __forceinline__ uint32_t frag_pack(const float* __restrict__ W,
                                              int N, int K32, int idx)
{
    const int blk  = idx >> 7;
    const int r    = idx & 127;
    const int lane = r >> 2;
    const int j    = r & 3;
    const int gid  = lane >> 2;
    const int tig  = lane & 3;
    const int n8   = blk / K32;
    const int t    = blk - n8 * K32;
    const int kp   = t*16 + tig + j*4;
    const int n    = n8*8 + gid;
    return packbf(W[(size_t)(2*kp)*N + n], W[(size_t)(2*kp+1)*N + n]);
}

__global__ __launch_bounds__(256) void wconv_all(WPackArgs a, uint32_t* __restrict__ out,
                                                 float* __restrict__ bcat)
{
    int idx = blockIdx.x * 256 + threadIdx.x;

    if (idx < 32768) { out[WP_WV + idx] = frag_pack(a.Wv, 256, 8, idx); return; }
    idx -= 32768;
    if (idx < 49152) {   // projcat K=256, N=384
        const int blk  = idx >> 7;
        const int r    = idx & 127;
        const int lane = r >> 2;
        const int j    = r & 3;
        const int gid  = lane >> 2;
        const int tig  = lane & 3;
        const int n8   = blk >> 3;
        const int t    = blk & 7;
        const int kp   = t*16 + tig + j*4;
        const int n    = n8*8 + gid;
        float lo, hi;
        if (n < 256) { lo = a.Woff[(size_t)(2*kp)*256 + n];      hi = a.Woff[(size_t)(2*kp+1)*256 + n]; }
        else         { lo = a.Wattn[(size_t)(2*kp)*128 + n-256]; hi = a.Wattn[(size_t)(2*kp+1)*128 + n-256]; }
        out[WP_PROJ + idx] = packbf(lo, hi);
        return;
    }
    idx -= 49152;
    if (idx < 32768) { out[WP_WOUT + idx] = frag_pack(a.Wout, 256, 8, idx); return; }
    idx -= 32768;
    if (idx < 131072) { out[WP_W1 + idx] = frag_pack(a.W1, 1024, 8, idx); return; }
    idx -= 131072;
    if (idx < 131072) { out[WP_W2 + idx] = frag_pack(a.W2, 256, 32, idx); return; }
    idx -= 131072;
    if (idx < 384) bcat[idx] = (idx < 256) ? a.boff[idx] : a.battn[idx - 256];
}

// ---------------- fragment-direct BF16 GEMM: no smem, no barriers ----------------
// C = A @ W + bias [...]; A = bf16 fragment layout, W = bf16 fragment layout.
// CTA: 128 threads = 4 warps over N; tile 64 x 128; K-step 16.
// OUT: 0 = fp32 row-major (+resid), 1 = fp16 row-major (+mask), 2 = fragment bf16 (+relu)
template<int OUT>
__global__ __launch_bounds__(128, 3) void gemm_fd(
    const uint32_t* __restrict__ Afd, const uint32_t* __restrict__ Wp,
    const float* __restrict__ bias, const float* __restrict__ resid,
    const uint8_t* __restrict__ mask, void* __restrict__ Cv,
    int M, int N, int K)
{
    const int tid   = threadIdx.x;
    const int warpN = tid >> 5;
    const int lane  = tid & 31;
    const int gid   = lane >> 2;
    const int tig   = lane & 3;
    const int row0  = blockIdx.y * 64;
    const int col0  = blockIdx.x * 128;
    const int K16   = K >> 4;
    const int K32   = K >> 5;
    const int mblk0 = row0 >> 4;
    const int nblk0 = (col0 >> 3) + warpN*4;

    float acc[4][4][4];
    #pragma unroll
    for (int i = 0; i < 4; i++)
        #pragma unroll
        for (int j = 0; j < 4; j++)
            #pragma unroll
            for (int r = 0; r < 4; r++) acc[i][j][r] = 0.f;

    uint4 af[2][4];
    uint2 bf[2][4];

    auto loadA = [&](uint4 (&dst)[4], int kblk) {
        #pragma unroll
        for (int mt = 0; mt < 4; mt++)
            dst[mt] = *(const uint4*)(Afd
                + (((size_t)(mblk0 + mt)*K16 + kblk) << 7) + (lane << 2));
    };
    auto loadB = [&](uint2 (&dst)[4], int t) {
        #pragma unroll
        for (int nt = 0; nt < 4; nt++)
            dst[nt] = *(const uint2*)(Wp
                + (((size_t)(nblk0 + nt)*K32 + (t >> 1)) << 7) + (lane << 2) + ((t & 1) << 1));
    };
    auto mmas = [&](const uint4 (&a)[4], const uint2 (&b)[4]) {
        #pragma unroll
        for (int mt = 0; mt < 4; mt++) {
            const uint32_t ar[4] = {a[mt].x, a[mt].y, a[mt].z, a[mt].w};
            #pragma unroll
            for (int nt = 0; nt < 4; nt++)
                mma_bf16(acc[mt][nt], ar, b[nt].x, b[nt].y);
        }
    };

    // prologue
    loadA(af[0], 0);
    loadA(af[1], 1);
    loadB(bf[0], 0);

    for (int t = 0; t < K16; t += 2) {
        loadB(bf[1], t + 1);
        mmas(af[0], bf[0]);
        if (t + 2 < K16) loadA(af[0], t + 2);

        if (t + 2 < K16) loadB(bf[0], t + 2);
        mmas(af[1], bf[1]);
        if (t + 3 < K16) loadA(af[1], t + 3);
    }

    // ---- epilogue ----
    if (OUT == 2) {
        // bias + relu, then store as next GEMM's A fragments
        const int K16o = N >> 4;
        #pragma unroll
        for (int mt = 0; mt < 4; mt++) {
            #pragma unroll
            for (int nt = 0; nt < 4; nt++) {
                const int c = col0 + warpN*32 + nt*8 + 2*tig;
                acc[mt][nt][0] = fmaxf(acc[mt][nt][0] + bias[c+0], 0.f);
                acc[mt][nt][1] = fmaxf(acc[mt][nt][1] + bias[c+1], 0.f);
                acc[mt][nt][2] = fmaxf(acc[mt][nt][2] + bias[c+0], 0.f);
                acc[mt][nt][3] = fmaxf(acc[mt][nt][3] + bias[c+1], 0.f);
            }
            #pragma unroll
            for (int q = 0; q < 2; q++) {
                const int kblk = ((col0 + warpN*32) >> 4) + q;
                uint4 w;
                w.x = packbf(acc[mt][2*q  ][0], acc[mt][2*q  ][1]);  // row gid,   k 0-7
                w.y = packbf(acc[mt][2*q  ][2], acc[mt][2*q  ][3]);  // row gid+8, k 0-7
                w.z = packbf(acc[mt][2*q+1][0], acc[mt][2*q+1][1]);  // row gid,   k 8-15
                w.w = packbf(acc[mt][2*q+1][2], acc[mt][2*q+1][3]);  // row gid+8, k 8-15
                *(uint4*)((uint32_t*)Cv
                    + (((size_t)(mblk0 + mt)*K16o + kblk) << 7) + (lane << 2)) = w;
            }
        }
    } else {
        #pragma unroll
        for (int mt = 0; mt < 4; mt++) {
            #pragma unroll
            for (int half = 0; half < 2; half++) {
                const int r = row0 + mt*16 + gid + half*8;
                if (r >= M) continue;
                const float mz = (OUT == 1 && mask && mask[r]) ? 0.f : 1.f;
                #pragma unroll
                for (int nt = 0; nt < 4; nt++) {
                    const int c = col0 + warpN*32 + nt*8 + 2*tig;
                    float v0 = acc[mt][nt][half*2 + 0] + bias[c + 0];
                    float v1 = acc[mt][nt][half*2 + 1] + bias[c + 1];
                    if (OUT == 0 && resid) {
                        const float* rp = resid + (size_t)r*N + c;
                        v0 += rp[0]; v1 += rp[1];
                    }
                    v0 *= mz; v1 *= mz;
                    if (OUT == 1) {
                        *(__half2*)((__half*)Cv + (size_t)r*N + c) = __floats2half2_rn(v0, v1);
                    } else {
                        *(float2*)((float*)Cv + (size_t)r*N + c) = make_float2(v0, v1);
                    }
                }
            }
        }
    }
}

// ---------------- fused loc + softmax + MS-deformable sampling ----------------
// out -> A fragments for the Wout GEMM (1 STG.32 per thread).
__global__ __launch_bounds__(128) void sample_kernel(
    const __half* __restrict__ value, const float* __restrict__ offattn,
    const float* __restrict__ ref,
    float* __restrict__ out_loc, uint32_t* __restrict__ outfd)
{
    __shared__ float s_loc[256];
    __shared__ float s_attn[128];

    const int bq   = blockIdx.x;
    const int tid  = threadIdx.x;
    const int b    = bq >> 11;

    #pragma unroll
    for (int i = 0; i < 2; i++) {
        const int j = tid + i*128;
        const int c = j & 1;
        const int l = (j >> 3) & 3;
        const float nd[4] = {100.f, 50.f, 25.f, 13.f};
        const float v = ref[((size_t)bq*4 + l)*2 + c]
                      + offattn[(size_t)bq*384 + j] / nd[l];
        s_loc[j] = v;
        out_loc[(size_t)bq*256 + j] = v;
    }
    {
        const float logit = offattn[(size_t)bq*384 + 256 + tid];
        float m = logit;
        #pragma unroll
        for (int o = 8; o; o >>= 1) m = fmaxf(m, __shfl_xor_sync(0xffffffffu, m, o, 16));
        const float e = __expf(logit - m);
        float s = e;
        #pragma unroll
        for (int o = 8; o; o >>= 1) s += __shfl_xor_sync(0xffffffffu, s, o, 16);
        s_attn[tid] = e / s;
    }
    __syncthreads();

    const int warp = tid >> 5;
    const int lane = tid & 31;
    const int h    = warp*2 + (lane >> 4);
    const int cp   = lane & 15;

    const float* locp = s_loc  + h*32;
    const float* ap   = s_attn + h*16;

    constexpr int LH[4] = {100, 50, 25, 13};
    constexpr int LS[4] = {0, 10000, 12500, 13125};

    float a0 = 0.f, a1 = 0.f;
    #pragma unroll
    for (int l = 0; l < 4; l++) {
        const int Hh = LH[l], Ww = LH[l];
        const __half2* vb = (const __half2*)(value
            + ((size_t)b*LEN_IN_ + LS[l])*DIM_ + h*32) + cp;
        #pragma unroll
        for (int p = 0; p < 4; p++) {
            const float lx = locp[(l*4 + p)*2 + 0];
            const float ly = locp[(l*4 + p)*2 + 1];
            const float a  = ap[l*4 + p];
            const float x = lx * (float)Ww - 0.5f;
            const float y = ly * (float)Hh - 0.5f;
            const float x0f = floorf(x), y0f = floorf(y);
            const float wx = x - x0f, wy = y - y0f;
            const int x0 = (int)x0f, y0 = (int)y0f;
            const int x1 = x0 + 1,  y1 = y0 + 1;

            const float vx0 = (x0 >= 0 && x0 < Ww) ? 1.f : 0.f;
            const float vx1 = (x1 >= 0 && x1 < Ww) ? 1.f : 0.f;
            const float vy0 = (y0 >= 0 && y0 < Hh) ? 1.f : 0.f;
            const float vy1 = (y1 >= 0 && y1 < Hh) ? 1.f : 0.f;
            const int cx0 = min(max(x0, 0), Ww-1);
            const int cx1 = min(max(x1, 0), Ww-1);
            const int cy0 = min(max(y0, 0), Hh-1);
            const int cy1 = min(max(y1, 0), Hh-1);

            const float2 g00 = __half22float2(vb[(size_t)(cy0*Ww + cx0)*128]);
            const float2 g01 = __half22float2(vb[(size_t)(cy0*Ww + cx1)*128]);
            const float2 g10 = __half22float2(vb[(size_t)(cy1*Ww + cx0)*128]);
            const float2 g11 = __half22float2(vb[(size_t)(cy1*Ww + cx1)*128]);

            const float w00 = vx0*vy0*(1.f-wx)*(1.f-wy);
            const float w01 = vx1*vy0*wx*(1.f-wy);
            const float w10 = vx0*vy1*(1.f-wx)*wy;
            const float w11 = vx1*vy1*wx*wy;

            a0 += a * (g00.x*w00 + g01.x*w01 + g10.x*w10 + g11.x*w11);
            a1 += a * (g00.y*w00 + g01.y*w01 + g10.y*w10 + g11.y*w11);
        }
    }
    outfd[afd_idx(bq, h*32 + cp*2, DIM_/16)] = packbf(a0, a1);
}

// ---------------- launch ----------------
extern "C" void kernel_launch(void* const* d_in, const int* in_sizes, int n_in,
                              void* d_out, int out_size)
{
    const float*   input  = (const float*)d_in[0];
    const float*   pos    = (const float*)d_in[1];
    const float*   refp   = (const float*)d_in[2];
    const float*   source = (const float*)d_in[3];
    const uint8_t* mask   = (const uint8_t*)d_in[6];
    const float*   ln1_g  = (const float*)d_in[7];
    const float*   ln1_b  = (const float*)d_in[8];
    const float*   ln2_g  = (const float*)d_in[9];
    const float*   ln2_b  = (const float*)d_in[10];
    const float*   Wv     = (const float*)d_in[11];
    const float*   bv     = (const float*)d_in[12];
    const float*   Woff   = (const float*)d_in[13];
    const float*   boff   = (const float*)d_in[14];
    const float*   Wattn  = (const float*)d_in[15];
    const float*   battn  = (const float*)d_in[16];
    const float*   Wout   = (const float*)d_in[17];
    const float*   bout   = (const float*)d_in[18];
    const float*   W1     = (const float*)d_in[19];
    const float*   b1     = (const float*)d_in[20];
    const float*   W2     = (const float*)d_in[21];
    const float*   b2     = (const float*)d_in[22];

    float* out_x   = (float*)d_out;
    float* out_loc = (float*)d_out + (size_t)BQ*DIM_;

    uint32_t *srcfd, *qpfd, *aofd, *ybfd, *ffnfd, *wp;
    float *offattn, *xb, *bcat;
    __half* valh;
    cudaGetSymbolAddress((void**)&srcfd,   g_src_fd);
    cudaGetSymbolAddress((void**)&qpfd,    g_qp_fd);
    cudaGetSymbolAddress((void**)&aofd,    g_attnout_fd);
    cudaGetSymbolAddress((void**)&ybfd,    g_yb_fd);
    cudaGetSymbolAddress((void**)&ffnfd,   g_ffn_fd);
    cudaGetSymbolAddress((void**)&valh,    g_valh);
    cudaGetSymbolAddress((void**)&offattn, g_offattn);
    cudaGetSymbolAddress((void**)&xb,      g_x);
    cudaGetSymbolAddress((void**)&wp,      g_wp);
    cudaGetSymbolAddress((void**)&bcat,    g_bcat);

    static cudaStream_t s1 = nullptr;
    static cudaEvent_t  e0 = nullptr, e1 = nullptr;
    if (s1 == nullptr) {
        cudaStreamCreateWithFlags(&s1, cudaStreamNonBlocking);
        cudaEventCreateWithFlags(&e0, cudaEventDisableTiming);
        cudaEventCreateWithFlags(&e1, cudaEventDisableTiming);
    }

    // 0) weight pack (B fragments) + bias concat
    {
        WPackArgs a{Wv, Woff, Wattn, Wout, W1, W2, boff, battn};
        wconv_all<<<(376832 + 384 + 255)/256, 256>>>(a, wp, bcat);
    }

    // fork: side stream does source pack + value GEMM
    cudaEventRecord(e0, 0);
    cudaStreamWaitEvent(s1, e0, 0);

    src_pack<<<(M_FD*128 + 255)/256, 256, 0, s1>>>(source, srcfd);
    gemm_fd<1><<<dim3(2, M_FD/64), 128, 0, s1>>>(srcfd, wp + WP_WV, bv, nullptr, mask,
                                                 valh, MV, DIM_, DIM_);
    cudaEventRecord(e1, s1);

    // main stream: LN1 -> proj
    ln_fd_kernel<<<BQ, 256>>>(input, ln1_g, ln1_b, pos, qpfd);
    gemm_fd<0><<<dim3(3, BQ/64), 128>>>(qpfd, wp + WP_PROJ, bcat, nullptr, nullptr,
                                        offattn, BQ, 384, DIM_);

    // join, then sampler
    cudaStreamWaitEvent(0, e1, 0);
    sample_kernel<<<BQ, 128>>>(valh, offattn, refp, out_loc, aofd);

    // x = input + attnout @ Wout + bout
    gemm_fd<0><<<dim3(2, BQ/64), 128>>>(aofd, wp + WP_WOUT, bout, input, nullptr,
                                        xb, BQ, DIM_, DIM_);

    // y = LN2(x) -> fragments
    ln_fd_kernel<<<BQ, 256>>>(xb, ln2_g, ln2_b, nullptr, ybfd);

    // ffn = relu(y @ W1 + b1) -> fragments
    gemm_fd<2><<<dim3(DFF/128, BQ/64), 128>>>(ybfd, wp + WP_W1, b1, nullptr, nullptr,
                                              ffnfd, BQ, DFF, DIM_);

    // out_x = x + ffn @ W2 + b2
    gemm_fd<0><<<dim3(2, BQ/64), 128>>>(ffnfd, wp + WP_W2, b2, xb, nullptr,
                                        out_x, BQ, DIM_, DFF);
}

// round 15
// speedup vs baseline: 1.0743x; 1.0743x over previous
#include <cuda_runtime.h>
#include <cuda_bf16.h>
#include <cuda_fp16.h>
#include <cstdint>

#define B_      8
#define Q_      2048
#define DIM_    256
#define NH      8
#define HD      32
#define DFF     1024
#define LEN_IN_ 13294
#define BQ      (B_*Q_)
#define MV      (B_*LEN_IN_)
#define M_FD    106368            // MV padded to 64

// ---------------- scratch ----------------
__device__ uint32_t g_src_fd[13615104];   // source as bf16 A-fragments (54.5 MB)
__device__ uint32_t g_qp_fd[2097152];     // LN1+pos as A-fragments
__device__ uint32_t g_attnout_fd[2097152];// sampler out as A-fragments
__device__ uint32_t g_yb_fd[2097152];     // LN2 out as A-fragments
__device__ uint32_t g_ffn_fd[8388608];    // FFN hidden as A-fragments (33.5 MB)
__device__ __half   g_valh[MV*DIM_];      // fp16 value (54 MB)
__device__ float    g_offattn[BQ*384];    // [off(256) | attn logits(128)]
__device__ float    g_x[BQ*DIM_];         // residual 1 (row-major fp32)
__device__ uint32_t g_wp[376832];         // packed bf16x2 weights (fragment layout)
__device__ float    g_bcat[384];          // concat bias [boff | battn]

#define WP_WV    0
#define WP_PROJ  32768
#define WP_WOUT  81920
#define WP_W1    114688
#define WP_W2    245760

// ---------------- helpers ----------------
__device__ __forceinline__ uint32_t packbf(float lo, float hi) {
    uint32_t d;
    asm("cvt.rn.bf16x2.f32 %0, %1, %2;" : "=r"(d) : "f"(hi), "f"(lo));
    return d;
}

__device__ __forceinline__ void mma_bf16(float c[4], const uint32_t a[4],
                                         uint32_t b0, uint32_t b1) {
    asm("mma.sync.aligned.m16n8k16.row.col.f32.bf16.bf16.f32 "
        "{%0,%1,%2,%3}, {%4,%5,%6,%7}, {%8,%9}, {%0,%1,%2,%3};"
        : "+f"(c[0]), "+f"(c[1]), "+f"(c[2]), "+f"(c[3])
        : "r"(a[0]), "r"(a[1]), "r"(a[2]), "r"(a[3]), "r"(b0), "r"(b1));
}

// A-fragment word index: ((mblk*K16 + kblk)*32 + lane)*4 + j
//   word j of lane (gid=lane>>2, tig=lane&3) holds bf16 pair
//   A[16*mblk + gid + 8*(j&1)][16*kblk + 2*tig + 8*((j>>1)&1) .. +1]
__device__ __forceinline__ size_t afd_idx(int row, int k, int K16) {
    const int mblk = row >> 4, rin = row & 15;
    const int kblk = k >> 4,  kk  = k & 15;
    const int j    = (rin >> 3) | ((kk >> 3) << 1);
    const int lane = (rin & 7) * 4 + ((kk & 7) >> 1);
    return ((size_t)(mblk * K16 + kblk) << 7) + (lane << 2) + j;
}

// store a lane's 8 contiguous elements (k0 = lane*8) of `row` as 4 frag words
__device__ __forceinline__ void frag_store8(uint32_t* __restrict__ outfd,
                                            int row, int lane, const float r[8])
{
    const int mblk = row >> 4, rin = row & 15;
    const int kblk  = lane >> 1;
    const int jbase = (rin >> 3) | ((lane & 1) << 1);
    uint32_t* base = outfd + ((size_t)(mblk*16 + kblk) << 7) + (((rin & 7) * 4) << 2) + jbase;
    #pragma unroll
    for (int i = 0; i < 4; i++)
        base[i << 2] = packbf(r[2*i], r[2*i+1]);
}

// ---------------- LayerNorm (+ optional addend) -> fragments; warp = row ----------------
__global__ __launch_bounds__(256) void ln_fd_kernel(
    const float* __restrict__ x, const float* __restrict__ g,
    const float* __restrict__ b, const float* __restrict__ addend,
    uint32_t* __restrict__ outfd)
{
    const int warp = threadIdx.x >> 5;
    const int lane = threadIdx.x & 31;
    const int row  = blockIdx.x * 8 + warp;
    const size_t off = (size_t)row * DIM_ + lane * 8;

    float v[8];
    {
        const float4 a = *(const float4*)(x + off);
        const float4 c = *(const float4*)(x + off + 4);
        v[0]=a.x; v[1]=a.y; v[2]=a.z; v[3]=a.w;
        v[4]=c.x; v[5]=c.y; v[6]=c.z; v[7]=c.w;
    }
    float s = 0.f;
    #pragma unroll
    for (int i = 0; i < 8; i++) s += v[i];
    #pragma unroll
    for (int o = 16; o; o >>= 1) s += __shfl_xor_sync(0xffffffffu, s, o);
    const float mean = s * (1.f/256.f);

    float s2 = 0.f;
    #pragma unroll
    for (int i = 0; i < 8; i++) { const float d = v[i] - mean; s2 += d*d; }
    #pragma unroll
    for (int o = 16; o; o >>= 1) s2 += __shfl_xor_sync(0xffffffffu, s2, o);
    const float inv = rsqrtf(s2 * (1.f/256.f) + 1e-5f);

    float r[8];
    {
        const int k = lane * 8;
        const float4 g0 = *(const float4*)(g + k);
        const float4 g1 = *(const float4*)(g + k + 4);
        const float4 b0 = *(const float4*)(b + k);
        const float4 b1 = *(const float4*)(b + k + 4);
        const float gg[8] = {g0.x,g0.y,g0.z,g0.w,g1.x,g1.y,g1.z,g1.w};
        const float bb[8] = {b0.x,b0.y,b0.z,b0.w,b1.x,b1.y,b1.z,b1.w};
        #pragma unroll
        for (int i = 0; i < 8; i++)
            r[i] = (v[i] - mean) * inv * gg[i] + bb[i];
        if (addend) {
            const float4 a0 = *(const float4*)(addend + off);
            const float4 a1 = *(const float4*)(addend + off + 4);
            const float aa[8] = {a0.x,a0.y,a0.z,a0.w,a1.x,a1.y,a1.z,a1.w};
            #pragma unroll
            for (int i = 0; i < 8; i++) r[i] += aa[i];
        }
    }
    frag_store8(outfd, row, lane, r);
}

// ---------------- source fp32 row-major -> A fragments; warp = row ----------------
__global__ __launch_bounds__(256) void src_pack(const float* __restrict__ src,
                                                uint32_t* __restrict__ outfd)
{
    const int warp = threadIdx.x >> 5;
    const int lane = threadIdx.x & 31;
    const int row  = blockIdx.x * 8 + warp;
    if (row >= M_FD) return;

    float r[8];
    if (row < MV) {
        const size_t off = (size_t)row * DIM_ + lane * 8;
        const float4 a = *(const float4*)(src + off);
        const float4 c = *(const float4*)(src + off + 4);
        r[0]=a.x; r[1]=a.y; r[2]=a.z; r[3]=a.w;
        r[4]=c.x; r[5]=c.y; r[6]=c.z; r[7]=c.w;
    } else {
        #pragma unroll
        for (int i = 0; i < 8; i++) r[i] = 0.f;
    }
    frag_store8(outfd, row, lane, r);
}

// ---------------- single-launch weight pack (B fragment layout) ----------------
struct WPackArgs {
    const float *Wv, *Woff, *Wattn, *Wout, *W1, *W2, *boff, *battn;
};

__device__ __forceinline__ uint32_t frag_pack(const float* __restrict__ W,
                                              int N, int K32, int idx)
{
    const int blk  = idx >> 7;
    const int r    = idx & 127;
    const int lane = r >> 2;
    const int j    = r & 3;
    const int gid  = lane >> 2;
    const int tig  = lane & 3;
    const int n8   = blk / K32;
    const int t    = blk - n8 * K32;
    const int kp   = t*16 + tig + j*4;
    const int n    = n8*8 + gid;
    return packbf(W[(size_t)(2*kp)*N + n], W[(size_t)(2*kp+1)*N + n]);
}

__global__ __launch_bounds__(256) void wconv_all(WPackArgs a, uint32_t* __restrict__ out,
                                                 float* __restrict__ bcat)
{
    int idx = blockIdx.x * 256 + threadIdx.x;

    if (idx < 32768) { out[WP_WV + idx] = frag_pack(a.Wv, 256, 8, idx); return; }
    idx -= 32768;
    if (idx < 49152) {   // projcat K=256, N=384
        const int blk  = idx >> 7;
        const int r    = idx & 127;
        const int lane = r >> 2;
        const int j    = r & 3;
        const int gid  = lane >> 2;
        const int tig  = lane & 3;
        const int n8   = blk >> 3;
        const int t    = blk & 7;
        const int kp   = t*16 + tig + j*4;
        const int n    = n8*8 + gid;
        float lo, hi;
        if (n < 256) { lo = a.Woff[(size_t)(2*kp)*256 + n];      hi = a.Woff[(size_t)(2*kp+1)*256 + n]; }
        else         { lo = a.Wattn[(size_t)(2*kp)*128 + n-256]; hi = a.Wattn[(size_t)(2*kp+1)*128 + n-256]; }
        out[WP_PROJ + idx] = packbf(lo, hi);
        return;
    }
    idx -= 49152;
    if (idx < 32768) { out[WP_WOUT + idx] = frag_pack(a.Wout, 256, 8, idx); return; }
    idx -= 32768;
    if (idx < 131072) { out[WP_W1 + idx] = frag_pack(a.W1, 1024, 8, idx); return; }
    idx -= 131072;
    if (idx < 131072) { out[WP_W2 + idx] = frag_pack(a.W2, 256, 32, idx); return; }
    idx -= 131072;
    if (idx < 384) bcat[idx] = (idx < 256) ? a.boff[idx] : a.battn[idx - 256];
}

// ---------------- fragment-direct BF16 GEMM: no smem, no barriers ----------------
// OUT: 0 = fp32 row-major (+resid), 1 = fp16 row-major (+mask), 2 = fragment bf16 (+relu)
template<int OUT>
__global__ __launch_bounds__(128, 3) void gemm_fd(
    const uint32_t* __restrict__ Afd, const uint32_t* __restrict__ Wp,
    const float* __restrict__ bias, const float* __restrict__ resid,
    const uint8_t* __restrict__ mask, void* __restrict__ Cv,
    int M, int N, int K)
{
    const int tid   = threadIdx.x;
    const int warpN = tid >> 5;
    const int lane  = tid & 31;
    const int gid   = lane >> 2;
    const int tig   = lane & 3;
    const int row0  = blockIdx.y * 64;
    const int col0  = blockIdx.x * 128;
    const int K16   = K >> 4;
    const int K32   = K >> 5;
    const int mblk0 = row0 >> 4;
    const int nblk0 = (col0 >> 3) + warpN*4;

    float acc[4][4][4];
    #pragma unroll
    for (int i = 0; i < 4; i++)
        #pragma unroll
        for (int j = 0; j < 4; j++)
            #pragma unroll
            for (int r = 0; r < 4; r++) acc[i][j][r] = 0.f;

    uint4 af[2][4];
    uint2 bf[2][4];

    auto loadA = [&](uint4 (&dst)[4], int kblk) {
        #pragma unroll
        for (int mt = 0; mt < 4; mt++)
            dst[mt] = *(const uint4*)(Afd
                + (((size_t)(mblk0 + mt)*K16 + kblk) << 7) + (lane << 2));
    };
    auto loadB = [&](uint2 (&dst)[4], int t) {
        #pragma unroll
        for (int nt = 0; nt < 4; nt++)
            dst[nt] = *(const uint2*)(Wp
                + (((size_t)(nblk0 + nt)*K32 + (t >> 1)) << 7) + (lane << 2) + ((t & 1) << 1));
    };
    auto mmas = [&](const uint4 (&a)[4], const uint2 (&b)[4]) {
        #pragma unroll
        for (int mt = 0; mt < 4; mt++) {
            const uint32_t ar[4] = {a[mt].x, a[mt].y, a[mt].z, a[mt].w};
            #pragma unroll
            for (int nt = 0; nt < 4; nt++)
                mma_bf16(acc[mt][nt], ar, b[nt].x, b[nt].y);
        }
    };

    loadA(af[0], 0);
    loadA(af[1], 1);
    loadB(bf[0], 0);

    for (int t = 0; t < K16; t += 2) {
        loadB(bf[1], t + 1);
        mmas(af[0], bf[0]);
        if (t + 2 < K16) loadA(af[0], t + 2);

        if (t + 2 < K16) loadB(bf[0], t + 2);
        mmas(af[1], bf[1]);
        if (t + 3 < K16) loadA(af[1], t + 3);
    }

    // ---- epilogue ----
    if (OUT == 2) {
        const int K16o = N >> 4;
        #pragma unroll
        for (int mt = 0; mt < 4; mt++) {
            #pragma unroll
            for (int nt = 0; nt < 4; nt++) {
                const int c = col0 + warpN*32 + nt*8 + 2*tig;
                acc[mt][nt][0] = fmaxf(acc[mt][nt][0] + bias[c+0], 0.f);
                acc[mt][nt][1] = fmaxf(acc[mt][nt][1] + bias[c+1], 0.f);
                acc[mt][nt][2] = fmaxf(acc[mt][nt][2] + bias[c+0], 0.f);
                acc[mt][nt][3] = fmaxf(acc[mt][nt][3] + bias[c+1], 0.f);
            }
            #pragma unroll
            for (int q = 0; q < 2; q++) {
                const int kblk = ((col0 + warpN*32) >> 4) + q;
                uint4 w;
                w.x = packbf(acc[mt][2*q  ][0], acc[mt][2*q  ][1]);
                w.y = packbf(acc[mt][2*q  ][2], acc[mt][2*q  ][3]);
                w.z = packbf(acc[mt][2*q+1][0], acc[mt][2*q+1][1]);
                w.w = packbf(acc[mt][2*q+1][2], acc[mt][2*q+1][3]);
                *(uint4*)((uint32_t*)Cv
                    + (((size_t)(mblk0 + mt)*K16o + kblk) << 7) + (lane << 2)) = w;
            }
        }
    } else {
        #pragma unroll
        for (int mt = 0; mt < 4; mt++) {
            #pragma unroll
            for (int half = 0; half < 2; half++) {
                const int r = row0 + mt*16 + gid + half*8;
                if (r >= M) continue;
                const float mz = (OUT == 1 && mask && mask[r]) ? 0.f : 1.f;
                #pragma unroll
                for (int nt = 0; nt < 4; nt++) {
                    const int c = col0 + warpN*32 + nt*8 + 2*tig;
                    float v0 = acc[mt][nt][half*2 + 0] + bias[c + 0];
                    float v1 = acc[mt][nt][half*2 + 1] + bias[c + 1];
                    if (OUT == 0 && resid) {
                        const float* rp = resid + (size_t)r*N + c;
                        v0 += rp[0]; v1 += rp[1];
                    }
                    v0 *= mz; v1 *= mz;
                    if (OUT == 1) {
                        *(__half2*)((__half*)Cv + (size_t)r*N + c) = __floats2half2_rn(v0, v1);
                    } else {
                        *(float2*)((float*)Cv + (size_t)r*N + c) = make_float2(v0, v1);
                    }
                }
            }
        }
    }
}

// ---------------- fused loc + softmax + MS-deformable sampling ----------------
__global__ __launch_bounds__(128) void sample_kernel(
    const __half* __restrict__ value, const float* __restrict__ offattn,
    const float* __restrict__ ref,
    float* __restrict__ out_loc, uint32_t* __restrict__ outfd)
{
    __shared__ float s_loc[256];
    __shared__ float s_attn[128];

    const int bq   = blockIdx.x;
    const int tid  = threadIdx.x;
    const int b    = bq >> 11;

    #pragma unroll
    for (int i = 0; i < 2; i++) {
        const int j = tid + i*128;
        const int c = j & 1;
        const int l = (j >> 3) & 3;
        const float nd[4] = {100.f, 50.f, 25.f, 13.f};
        const float v = ref[((size_t)bq*4 + l)*2 + c]
                      + offattn[(size_t)bq*384 + j] / nd[l];
        s_loc[j] = v;
        out_loc[(size_t)bq*256 + j] = v;
    }
    {
        const float logit = offattn[(size_t)bq*384 + 256 + tid];
        float m = logit;
        #pragma unroll
        for (int o = 8; o; o >>= 1) m = fmaxf(m, __shfl_xor_sync(0xffffffffu, m, o, 16));
        const float e = __expf(logit - m);
        float s = e;
        #pragma unroll
        for (int o = 8; o; o >>= 1) s += __shfl_xor_sync(0xffffffffu, s, o, 16);
        s_attn[tid] = e / s;
    }
    __syncthreads();

    const int warp = tid >> 5;
    const int lane = tid & 31;
    const int h    = warp*2 + (lane >> 4);
    const int cp   = lane & 15;

    const float* locp = s_loc  + h*32;
    const float* ap   = s_attn + h*16;

    constexpr int LH[4] = {100, 50, 25, 13};
    constexpr int LS[4] = {0, 10000, 12500, 13125};

    float a0 = 0.f, a1 = 0.f;
    #pragma unroll
    for (int l = 0; l < 4; l++) {
        const int Hh = LH[l], Ww = LH[l];
        const __half2* vb = (const __half2*)(value
            + ((size_t)b*LEN_IN_ + LS[l])*DIM_ + h*32) + cp;
        #pragma unroll
        for (int p = 0; p < 4; p++) {
            const float lx = locp[(l*4 + p)*2 + 0];
            const float ly = locp[(l*4 + p)*2 + 1];
            const float a  = ap[l*4 + p];
            const float x = lx * (float)Ww - 0.5f;
            const float y = ly * (float)Hh - 0.5f;
            const float x0f = floorf(x), y0f = floorf(y);
            const float wx = x - x0f, wy = y - y0f;
            const int x0 = (int)x0f, y0 = (int)y0f;
            const int x1 = x0 + 1,  y1 = y0 + 1;

            const float vx0 = (x0 >= 0 && x0 < Ww) ? 1.f : 0.f;
            const float vx1 = (x1 >= 0 && x1 < Ww) ? 1.f : 0.f;
            const float vy0 = (y0 >= 0 && y0 < Hh) ? 1.f : 0.f;
            const float vy1 = (y1 >= 0 && y1 < Hh) ? 1.f : 0.f;
            const int cx0 = min(max(x0, 0), Ww-1);
            const int cx1 = min(max(x1, 0), Ww-1);
            const int cy0 = min(max(y0, 0), Hh-1);
            const int cy1 = min(max(y1, 0), Hh-1);

            const float2 g00 = __half22float2(vb[(size_t)(cy0*Ww + cx0)*128]);
            const float2 g01 = __half22float2(vb[(size_t)(cy0*Ww + cx1)*128]);
            const float2 g10 = __half22float2(vb[(size_t)(cy1*Ww + cx0)*128]);
            const float2 g11 = __half22float2(vb[(size_t)(cy1*Ww + cx1)*128]);

            const float w00 = vx0*vy0*(1.f-wx)*(1.f-wy);
            const float w01 = vx1*vy0*wx*(1.f-wy);
            const float w10 = vx0*vy1*(1.f-wx)*wy;
            const float w11 = vx1*vy1*wx*wy;

            a0 += a * (g00.x*w00 + g01.x*w01 + g10.x*w10 + g11.x*w11);
            a1 += a * (g00.y*w00 + g01.y*w01 + g10.y*w10 + g11.y*w11);
        }
    }
    outfd[afd_idx(bq, h*32 + cp*2, DIM_/16)] = packbf(a0, a1);
}

// ---------------- launch ----------------
extern "C" void kernel_launch(void* const* d_in, const int* in_sizes, int n_in,
                              void* d_out, int out_size)
{
    const float*   input  = (const float*)d_in[0];
    const float*   pos    = (const float*)d_in[1];
    const float*   refp   = (const float*)d_in[2];
    const float*   source = (const float*)d_in[3];
    const uint8_t* mask   = (const uint8_t*)d_in[6];
    const float*   ln1_g  = (const float*)d_in[7];
    const float*   ln1_b  = (const float*)d_in[8];
    const float*   ln2_g  = (const float*)d_in[9];
    const float*   ln2_b  = (const float*)d_in[10];
    const float*   Wv     = (const float*)d_in[11];
    const float*   bv     = (const float*)d_in[12];
    const float*   Woff   = (const float*)d_in[13];
    const float*   boff   = (const float*)d_in[14];
    const float*   Wattn  = (const float*)d_in[15];
    const float*   battn  = (const float*)d_in[16];
    const float*   Wout   = (const float*)d_in[17];
    const float*   bout   = (const float*)d_in[18];
    const float*   W1     = (const float*)d_in[19];
    const float*   b1     = (const float*)d_in[20];
    const float*   W2     = (const float*)d_in[21];
    const float*   b2     = (const float*)d_in[22];

    float* out_x   = (float*)d_out;
    float* out_loc = (float*)d_out + (size_t)BQ*DIM_;

    uint32_t *srcfd, *qpfd, *aofd, *ybfd, *ffnfd, *wp;
    float *offattn, *xb, *bcat;
    __half* valh;
    cudaGetSymbolAddress((void**)&srcfd,   g_src_fd);
    cudaGetSymbolAddress((void**)&qpfd,    g_qp_fd);
    cudaGetSymbolAddress((void**)&aofd,    g_attnout_fd);
    cudaGetSymbolAddress((void**)&ybfd,    g_yb_fd);
    cudaGetSymbolAddress((void**)&ffnfd,   g_ffn_fd);
    cudaGetSymbolAddress((void**)&valh,    g_valh);
    cudaGetSymbolAddress((void**)&offattn, g_offattn);
    cudaGetSymbolAddress((void**)&xb,      g_x);
    cudaGetSymbolAddress((void**)&wp,      g_wp);
    cudaGetSymbolAddress((void**)&bcat,    g_bcat);

    static cudaStream_t s1 = nullptr;
    static cudaEvent_t  e0 = nullptr, ew = nullptr, e1 = nullptr;
    if (s1 == nullptr) {
        cudaStreamCreateWithFlags(&s1, cudaStreamNonBlocking);
        cudaEventCreateWithFlags(&e0, cudaEventDisableTiming);
        cudaEventCreateWithFlags(&ew, cudaEventDisableTiming);
        cudaEventCreateWithFlags(&e1, cudaEventDisableTiming);
    }

    // fork immediately: src_pack depends on nothing
    cudaEventRecord(e0, 0);
    cudaStreamWaitEvent(s1, e0, 0);
    src_pack<<<M_FD/8, 256, 0, s1>>>(source, srcfd);

    // 0) weight pack (B fragments) + bias concat   [main stream]
    {
        WPackArgs a{Wv, Woff, Wattn, Wout, W1, W2, boff, battn};
        wconv_all<<<(376832 + 384 + 255)/256, 256>>>(a, wp, bcat);
    }
    cudaEventRecord(ew, 0);
    cudaStreamWaitEvent(s1, ew, 0);

    // value GEMM on side stream (needs srcfd + wp)
    gemm_fd<1><<<dim3(2, M_FD/64), 128, 0, s1>>>(srcfd, wp + WP_WV, bv, nullptr, mask,
                                                 valh, MV, DIM_, DIM_);
    cudaEventRecord(e1, s1);

    // main stream: LN1 -> proj
    ln_fd_kernel<<<BQ/8, 256>>>(input, ln1_g, ln1_b, pos, qpfd);
    gemm_fd<0><<<dim3(3, BQ/64), 128>>>(qpfd, wp + WP_PROJ, bcat, nullptr, nullptr,
                                        offattn, BQ, 384, DIM_);

    // join, then sampler
    cudaStreamWaitEvent(0, e1, 0);
    sample_kernel<<<BQ, 128>>>(valh, offattn, refp, out_loc, aofd);

    // x = input + attnout @ Wout + bout
    gemm_fd<0><<<dim3(2, BQ/64), 128>>>(aofd, wp + WP_WOUT, bout, input, nullptr,
                                        xb, BQ, DIM_, DIM_);

    // y = LN2(x) -> fragments
    ln_fd_kernel<<<BQ/8, 256>>>(xb, ln2_g, ln2_b, nullptr, ybfd);

    // ffn = relu(y @ W1 + b1) -> fragments
    gemm_fd<2><<<dim3(DFF/128, BQ/64), 128>>>(ybfd, wp + WP_W1, b1, nullptr, nullptr,
                                              ffnfd, BQ, DFF, DIM_);

    // out_x = x + ffn @ W2 + b2
    gemm_fd<0><<<dim3(2, BQ/64), 128>>>(ffnfd, wp + WP_W2, b2, xb, nullptr,
                                        out_x, BQ, DIM_, DFF);
}

// round 16
// speedup vs baseline: 1.0813x; 1.0066x over previous
#include <cuda_runtime.h>
#include <cuda_bf16.h>
#include <cuda_fp16.h>
#include <cstdint>

#define B_      8
#define Q_      2048
#define DIM_    256
#define NH      8
#define HD      32
#define DFF     1024
#define LEN_IN_ 13294
#define BQ      (B_*Q_)
#define MV      (B_*LEN_IN_)
#define M_FD    106368            // MV padded to 64 (and 16)

// ---------------- scratch ----------------
__device__ uint32_t g_src_fd[13615104];   // source as bf16 A-fragments (54.5 MB)
__device__ uint32_t g_qp_fd[2097152];     // LN1+pos as A-fragments
__device__ uint32_t g_attnout_fd[2097152];// sampler out as A-fragments
__device__ uint32_t g_yb_fd[2097152];     // LN2 out as A-fragments
__device__ uint32_t g_ffn_fd[8388608];    // FFN hidden as A-fragments (33.5 MB)
__device__ __half   g_valh[MV*DIM_];      // fp16 value (54 MB)
__device__ float    g_offattn[BQ*384];    // [off(256) | attn logits(128)]
__device__ float    g_x[BQ*DIM_];         // residual 1 (row-major fp32)
__device__ uint32_t g_wp[376832];         // packed bf16x2 weights (fragment layout)
__device__ float    g_bcat[384];          // concat bias [boff | battn]

#define WP_WV    0
#define WP_PROJ  32768
#define WP_WOUT  81920
#define WP_W1    114688
#define WP_W2    245760

// ---------------- helpers ----------------
__device__ __forceinline__ uint32_t packbf(float lo, float hi) {
    uint32_t d;
    asm("cvt.rn.bf16x2.f32 %0, %1, %2;" : "=r"(d) : "f"(hi), "f"(lo));
    return d;
}

__device__ __forceinline__ void mma_bf16(float c[4], const uint32_t a[4],
                                         uint32_t b0, uint32_t b1) {
    asm("mma.sync.aligned.m16n8k16.row.col.f32.bf16.bf16.f32 "
        "{%0,%1,%2,%3}, {%4,%5,%6,%7}, {%8,%9}, {%0,%1,%2,%3};"
        : "+f"(c[0]), "+f"(c[1]), "+f"(c[2]), "+f"(c[3])
        : "r"(a[0]), "r"(a[1]), "r"(a[2]), "r"(a[3]), "r"(b0), "r"(b1));
}

// A-fragment word index: ((mblk*K16 + kblk)*32 + lane)*4 + j
//   word j of lane (gid=lane>>2, tig=lane&3) holds bf16 pair
//   A[16*mblk + gid + 8*(j&1)][16*kblk + 2*tig + 8*((j>>1)&1) .. +1]
__device__ __forceinline__ size_t afd_idx(int row, int k, int K16) {
    const int mblk = row >> 4, rin = row & 15;
    const int kblk = k >> 4,  kk  = k & 15;
    const int j    = (rin >> 3) | ((kk >> 3) << 1);
    const int lane = (rin & 7) * 4 + ((kk & 7) >> 1);
    return ((size_t)(mblk * K16 + kblk) << 7) + (lane << 2) + j;
}

// emit fragments for one 16-row mblk from an smem fp32 tile (coalesced STG.128)
#define SPAD 264
__device__ __forceinline__ void emit_mblk(const float* __restrict__ s,  // [16][SPAD]
                                          uint32_t* __restrict__ outfd,
                                          int mblk, int tid)
{
    #pragma unroll
    for (int task = tid; task < 512; task += 256) {
        const int kblk   = task >> 5;
        const int lane_t = task & 31;
        const int gid    = lane_t >> 2;
        const int tig    = lane_t & 3;
        uint4 w;
        uint32_t* wv = (uint32_t*)&w;
        #pragma unroll
        for (int j = 0; j < 4; j++) {
            const int row_l = gid + ((j & 1) << 3);
            const int k     = kblk*16 + 2*tig + ((j >> 1) << 3);
            const float2 v  = *(const float2*)(s + row_l*SPAD + k);
            wv[j] = packbf(v.x, v.y);
        }
        *(uint4*)(outfd + (((size_t)(mblk*16 + kblk)) << 7) + (lane_t << 2)) = w;
    }
}

// ---------------- LayerNorm (+ optional addend) -> fragments ----------------
// block = 16 rows (one mblk), 256 threads; half-warp per row for LN, then
// coalesced fragment emission via smem.
__global__ __launch_bounds__(256) void ln_fd_kernel(
    const float* __restrict__ x, const float* __restrict__ g,
    const float* __restrict__ b, const float* __restrict__ addend,
    uint32_t* __restrict__ outfd)
{
    __shared__ float s[16*SPAD];
    const int tid    = threadIdx.x;
    const int lane   = tid & 31;
    const int rowl   = (tid >> 4);            // 0..15 (half-warp per row)
    const int lane16 = tid & 15;
    const int row    = blockIdx.x * 16 + rowl;
    const size_t off = (size_t)row * DIM_ + lane16 * 16;

    float v[16];
    #pragma unroll
    for (int q = 0; q < 4; q++) {
        const float4 a = *(const float4*)(x + off + q*4);
        v[q*4+0]=a.x; v[q*4+1]=a.y; v[q*4+2]=a.z; v[q*4+3]=a.w;
    }
    float sum = 0.f;
    #pragma unroll
    for (int i = 0; i < 16; i++) sum += v[i];
    #pragma unroll
    for (int o = 8; o; o >>= 1) sum += __shfl_xor_sync(0xffffffffu, sum, o, 16);
    const float mean = sum * (1.f/256.f);

    float s2 = 0.f;
    #pragma unroll
    for (int i = 0; i < 16; i++) { const float d = v[i] - mean; s2 += d*d; }
    #pragma unroll
    for (int o = 8; o; o >>= 1) s2 += __shfl_xor_sync(0xffffffffu, s2, o, 16);
    const float inv = rsqrtf(s2 * (1.f/256.f) + 1e-5f);

    {
        const int k = lane16 * 16;
        #pragma unroll
        for (int q = 0; q < 4; q++) {
            const float4 gg = *(const float4*)(g + k + q*4);
            const float4 bb = *(const float4*)(b + k + q*4);
            v[q*4+0] = (v[q*4+0]-mean)*inv*gg.x + bb.x;
            v[q*4+1] = (v[q*4+1]-mean)*inv*gg.y + bb.y;
            v[q*4+2] = (v[q*4+2]-mean)*inv*gg.z + bb.z;
            v[q*4+3] = (v[q*4+3]-mean)*inv*gg.w + bb.w;
        }
        if (addend) {
            #pragma unroll
            for (int q = 0; q < 4; q++) {
                const float4 aa = *(const float4*)(addend + off + q*4);
                v[q*4+0] += aa.x; v[q*4+1] += aa.y;
                v[q*4+2] += aa.z; v[q*4+3] += aa.w;
            }
        }
        float* sp = s + rowl*SPAD + k;
        #pragma unroll
        for (int q = 0; q < 4; q++)
            *(float4*)(sp + q*4) = make_float4(v[q*4+0], v[q*4+1], v[q*4+2], v[q*4+3]);
    }
    __syncthreads();
    emit_mblk(s, outfd, blockIdx.x, tid);
    (void)lane;
}

// ---------------- source fp32 row-major -> A fragments (coalesced) ----------------
__global__ __launch_bounds__(256) void src_pack(const float* __restrict__ src,
                                                uint32_t* __restrict__ outfd)
{
    __shared__ float s[16*SPAD];
    const int tid  = threadIdx.x;
    const int rowl = tid >> 4;
    const int k0   = (tid & 15) * 16;
    const int row  = blockIdx.x * 16 + rowl;

    if (row < MV) {
        const size_t off = (size_t)row * DIM_ + k0;
        float* sp = s + rowl*SPAD + k0;
        #pragma unroll
        for (int q = 0; q < 4; q++)
            *(float4*)(sp + q*4) = *(const float4*)(src + off + q*4);
    } else {
        float* sp = s + rowl*SPAD + k0;
        #pragma unroll
        for (int q = 0; q < 4; q++)
            *(float4*)(sp + q*4) = make_float4(0.f, 0.f, 0.f, 0.f);
    }
    __syncthreads();
    emit_mblk(s, outfd, blockIdx.x, tid);
}

// ---------------- single-launch weight pack (B fragment layout) ----------------
struct WPackArgs {
    const float *Wv, *Woff, *Wattn, *Wout, *W1, *W2, *boff, *battn;
};

__device__ __forceinline__ uint32_t frag_pack(const float* __restrict__ W,
                                              int N, int K32, int idx)
{
    const int blk  = idx >> 7;
    const int r    = idx & 127;
    const int lane = r >> 2;
    const int j    = r & 3;
    const int gid  = lane >> 2;
    const int tig  = lane & 3;
    const int n8   = blk / K32;
    const int t    = blk - n8 * K32;
    const int kp   = t*16 + tig + j*4;
    const int n    = n8*8 + gid;
    return packbf(W[(size_t)(2*kp)*N + n], W[(size_t)(2*kp+1)*N + n]);
}

__global__ __launch_bounds__(256) void wconv_all(WPackArgs a, uint32_t* __restrict__ out,
                                                 float* __restrict__ bcat)
{
    int idx = blockIdx.x * 256 + threadIdx.x;

    if (idx < 32768) { out[WP_WV + idx] = frag_pack(a.Wv, 256, 8, idx); return; }
    idx -= 32768;
    if (idx < 49152) {   // projcat K=256, N=384
        const int blk  = idx >> 7;
        const int r    = idx & 127;
        const int lane = r >> 2;
        const int j    = r & 3;
        const int gid  = lane >> 2;
        const int tig  = lane & 3;
        const int n8   = blk >> 3;
        const int t    = blk & 7;
        const int kp   = t*16 + tig + j*4;
        const int n    = n8*8 + gid;
        float lo, hi;
        if (n < 256) { lo = a.Woff[(size_t)(2*kp)*256 + n];      hi = a.Woff[(size_t)(2*kp+1)*256 + n]; }
        else         { lo = a.Wattn[(size_t)(2*kp)*128 + n-256]; hi = a.Wattn[(size_t)(2*kp+1)*128 + n-256]; }
        out[WP_PROJ + idx] = packbf(lo, hi);
        return;
    }
    idx -= 49152;
    if (idx < 32768) { out[WP_WOUT + idx] = frag_pack(a.Wout, 256, 8, idx); return; }
    idx -= 32768;
    if (idx < 131072) { out[WP_W1 + idx] = frag_pack(a.W1, 1024, 8, idx); return; }
    idx -= 131072;
    if (idx < 131072) { out[WP_W2 + idx] = frag_pack(a.W2, 256, 32, idx); return; }
    idx -= 131072;
    if (idx < 384) bcat[idx] = (idx < 256) ? a.boff[idx] : a.battn[idx - 256];
}

// ---------------- fragment-direct BF16 GEMM: no smem, no barriers ----------------
// OUT: 0 = fp32 row-major (+resid), 1 = fp16 row-major (+mask), 2 = fragment bf16 (+relu)
template<int OUT>
__global__ __launch_bounds__(128, 3) void gemm_fd(
    const uint32_t* __restrict__ Afd, const uint32_t* __restrict__ Wp,
    const float* __restrict__ bias, const float* __restrict__ resid,
    const uint8_t* __restrict__ mask, void* __restrict__ Cv,
    int M, int N, int K)
{
    const int tid   = threadIdx.x;
    const int warpN = tid >> 5;
    const int lane  = tid & 31;
    const int gid   = lane >> 2;
    const int tig   = lane & 3;
    const int row0  = blockIdx.y * 64;
    const int col0  = blockIdx.x * 128;
    const int K16   = K >> 4;
    const int K32   = K >> 5;
    const int mblk0 = row0 >> 4;
    const int nblk0 = (col0 >> 3) + warpN*4;

    float acc[4][4][4];
    #pragma unroll
    for (int i = 0; i < 4; i++)
        #pragma unroll
        for (int j = 0; j < 4; j++)
            #pragma unroll
            for (int r = 0; r < 4; r++) acc[i][j][r] = 0.f;

    uint4 af[2][4];
    uint2 bf[2][4];

    auto loadA = [&](uint4 (&dst)[4], int kblk) {
        #pragma unroll
        for (int mt = 0; mt < 4; mt++)
            dst[mt] = *(const uint4*)(Afd
                + (((size_t)(mblk0 + mt)*K16 + kblk) << 7) + (lane << 2));
    };
    auto loadB = [&](uint2 (&dst)[4], int t) {
        #pragma unroll
        for (int nt = 0; nt < 4; nt++)
            dst[nt] = *(const uint2*)(Wp
                + (((size_t)(nblk0 + nt)*K32 + (t >> 1)) << 7) + (lane << 2) + ((t & 1) << 1));
    };
    auto mmas = [&](const uint4 (&a)[4], const uint2 (&b)[4]) {
        #pragma unroll
        for (int mt = 0; mt < 4; mt++) {
            const uint32_t ar[4] = {a[mt].x, a[mt].y, a[mt].z, a[mt].w};
            #pragma unroll
            for (int nt = 0; nt < 4; nt++)
                mma_bf16(acc[mt][nt], ar, b[nt].x, b[nt].y);
        }
    };

    loadA(af[0], 0);
    loadA(af[1], 1);
    loadB(bf[0], 0);

    for (int t = 0; t < K16; t += 2) {
        loadB(bf[1], t + 1);
        mmas(af[0], bf[0]);
        if (t + 2 < K16) loadA(af[0], t + 2);

        if (t + 2 < K16) loadB(bf[0], t + 2);
        mmas(af[1], bf[1]);
        if (t + 3 < K16) loadA(af[1], t + 3);
    }

    // ---- epilogue ----
    if (OUT == 2) {
        const int K16o = N >> 4;
        #pragma unroll
        for (int mt = 0; mt < 4; mt++) {
            #pragma unroll
            for (int nt = 0; nt < 4; nt++) {
                const int c = col0 + warpN*32 + nt*8 + 2*tig;
                acc[mt][nt][0] = fmaxf(acc[mt][nt][0] + bias[c+0], 0.f);
                acc[mt][nt][1] = fmaxf(acc[mt][nt][1] + bias[c+1], 0.f);
                acc[mt][nt][2] = fmaxf(acc[mt][nt][2] + bias[c+0], 0.f);
                acc[mt][nt][3] = fmaxf(acc[mt][nt][3] + bias[c+1], 0.f);
            }
            #pragma unroll
            for (int q = 0; q < 2; q++) {
                const int kblk = ((col0 + warpN*32) >> 4) + q;
                uint4 w;
                w.x = packbf(acc[mt][2*q  ][0], acc[mt][2*q  ][1]);
                w.y = packbf(acc[mt][2*q  ][2], acc[mt][2*q  ][3]);
                w.z = packbf(acc[mt][2*q+1][0], acc[mt][2*q+1][1]);
                w.w = packbf(acc[mt][2*q+1][2], acc[mt][2*q+1][3]);
                *(uint4*)((uint32_t*)Cv
                    + (((size_t)(mblk0 + mt)*K16o + kblk) << 7) + (lane << 2)) = w;
            }
        }
    } else {
        #pragma unroll
        for (int mt = 0; mt < 4; mt++) {
            #pragma unroll
            for (int half = 0; half < 2; half++) {
                const int r = row0 + mt*16 + gid + half*8;
                if (r >= M) continue;
                const float mz = (OUT == 1 && mask && mask[r]) ? 0.f : 1.f;
                #pragma unroll
                for (int nt = 0; nt < 4; nt++) {
                    const int c = col0 + warpN*32 + nt*8 + 2*tig;
                    float v0 = acc[mt][nt][half*2 + 0] + bias[c + 0];
                    float v1 = acc[mt][nt][half*2 + 1] + bias[c + 1];
                    if (OUT == 0 && resid) {
                        const float* rp = resid + (size_t)r*N + c;
                        v0 += rp[0]; v1 += rp[1];
                    }
                    v0 *= mz; v1 *= mz;
                    if (OUT == 1) {
                        *(__half2*)((__half*)Cv + (size_t)r*N + c) = __floats2half2_rn(v0, v1);
                    } else {
                        *(float2*)((float*)Cv + (size_t)r*N + c) = make_float2(v0, v1);
                    }
                }
            }
        }
    }
}

// ---------------- fused loc + softmax + MS-deformable sampling ----------------
__global__ __launch_bounds__(128) void sample_kernel(
    const __half* __restrict__ value, const float* __restrict__ offattn,
    const float* __restrict__ ref,
    float* __restrict__ out_loc, uint32_t* __restrict__ outfd)
{
    __shared__ float s_loc[256];
    __shared__ float s_attn[128];

    const int bq   = blockIdx.x;
    const int tid  = threadIdx.x;
    const int b    = bq >> 11;

    #pragma unroll
    for (int i = 0; i < 2; i++) {
        const int j = tid + i*128;
        const int c = j & 1;
        const int l = (j >> 3) & 3;
        const float nd[4] = {100.f, 50.f, 25.f, 13.f};
        const float v = ref[((size_t)bq*4 + l)*2 + c]
                      + offattn[(size_t)bq*384 + j] / nd[l];
        s_loc[j] = v;
        out_loc[(size_t)bq*256 + j] = v;
    }
    {
        const float logit = offattn[(size_t)bq*384 + 256 + tid];
        float m = logit;
        #pragma unroll
        for (int o = 8; o; o >>= 1) m = fmaxf(m, __shfl_xor_sync(0xffffffffu, m, o, 16));
        const float e = __expf(logit - m);
        float s = e;
        #pragma unroll
        for (int o = 8; o; o >>= 1) s += __shfl_xor_sync(0xffffffffu, s, o, 16);
        s_attn[tid] = e / s;
    }
    __syncthreads();

    const int warp = tid >> 5;
    const int lane = tid & 31;
    const int h    = warp*2 + (lane >> 4);
    const int cp   = lane & 15;

    const float* locp = s_loc  + h*32;
    const float* ap   = s_attn + h*16;

    constexpr int LH[4] = {100, 50, 25, 13};
    constexpr int LS[4] = {0, 10000, 12500, 13125};

    float a0 = 0.f, a1 = 0.f;
    #pragma unroll
    for (int l = 0; l < 4; l++) {
        const int Hh = LH[l], Ww = LH[l];
        const __half2* vb = (const __half2*)(value
            + ((size_t)b*LEN_IN_ + LS[l])*DIM_ + h*32) + cp;
        #pragma unroll
        for (int p = 0; p < 4; p++) {
            const float lx = locp[(l*4 + p)*2 + 0];
            const float ly = locp[(l*4 + p)*2 + 1];
            const float a  = ap[l*4 + p];
            const float x = lx * (float)Ww - 0.5f;
            const float y = ly * (float)Hh - 0.5f;
            const float x0f = floorf(x), y0f = floorf(y);
            const float wx = x - x0f, wy = y - y0f;
            const int x0 = (int)x0f, y0 = (int)y0f;
            const int x1 = x0 + 1,  y1 = y0 + 1;

            const float vx0 = (x0 >= 0 && x0 < Ww) ? 1.f : 0.f;
            const float vx1 = (x1 >= 0 && x1 < Ww) ? 1.f : 0.f;
            const float vy0 = (y0 >= 0 && y0 < Hh) ? 1.f : 0.f;
            const float vy1 = (y1 >= 0 && y1 < Hh) ? 1.f : 0.f;
            const int cx0 = min(max(x0, 0), Ww-1);
            const int cx1 = min(max(x1, 0), Ww-1);
            const int cy0 = min(max(y0, 0), Hh-1);
            const int cy1 = min(max(y1, 0), Hh-1);

            const float2 g00 = __half22float2(vb[(size_t)(cy0*Ww + cx0)*128]);
            const float2 g01 = __half22float2(vb[(size_t)(cy0*Ww + cx1)*128]);
            const float2 g10 = __half22float2(vb[(size_t)(cy1*Ww + cx0)*128]);
            const float2 g11 = __half22float2(vb[(size_t)(cy1*Ww + cx1)*128]);

            const float w00 = vx0*vy0*(1.f-wx)*(1.f-wy);
            const float w01 = vx1*vy0*wx*(1.f-wy);
            const float w10 = vx0*vy1*(1.f-wx)*wy;
            const float w11 = vx1*vy1*wx*wy;

            a0 += a * (g00.x*w00 + g01.x*w01 + g10.x*w10 + g11.x*w11);
            a1 += a * (g00.y*w00 + g01.y*w01 + g10.y*w10 + g11.y*w11);
        }
    }
    outfd[afd_idx(bq, h*32 + cp*2, DIM_/16)] = packbf(a0, a1);
}

// ---------------- launch ----------------
extern "C" void kernel_launch(void* const* d_in, const int* in_sizes, int n_in,
                              void* d_out, int out_size)
{
    const float*   input  = (const float*)d_in[0];
    const float*   pos    = (const float*)d_in[1];
    const float*   refp   = (const float*)d_in[2];
    const float*   source = (const float*)d_in[3];
    const uint8_t* mask   = (const uint8_t*)d_in[6];
    const float*   ln1_g  = (const float*)d_in[7];
    const float*   ln1_b  = (const float*)d_in[8];
    const float*   ln2_g  = (const float*)d_in[9];
    const float*   ln2_b  = (const float*)d_in[10];
    const float*   Wv     = (const float*)d_in[11];
    const float*   bv     = (const float*)d_in[12];
    const float*   Woff   = (const float*)d_in[13];
    const float*   boff   = (const float*)d_in[14];
    const float*   Wattn  = (const float*)d_in[15];
    const float*   battn  = (const float*)d_in[16];
    const float*   Wout   = (const float*)d_in[17];
    const float*   bout   = (const float*)d_in[18];
    const float*   W1     = (const float*)d_in[19];
    const float*   b1     = (const float*)d_in[20];
    const float*   W2     = (const float*)d_in[21];
    const float*   b2     = (const float*)d_in[22];

    float* out_x   = (float*)d_out;
    float* out_loc = (float*)d_out + (size_t)BQ*DIM_;

    uint32_t *srcfd, *qpfd, *aofd, *ybfd, *ffnfd, *wp;
    float *offattn, *xb, *bcat;
    __half* valh;
    cudaGetSymbolAddress((void**)&srcfd,   g_src_fd);
    cudaGetSymbolAddress((void**)&qpfd,    g_qp_fd);
    cudaGetSymbolAddress((void**)&aofd,    g_attnout_fd);
    cudaGetSymbolAddress((void**)&ybfd,    g_yb_fd);
    cudaGetSymbolAddress((void**)&ffnfd,   g_ffn_fd);
    cudaGetSymbolAddress((void**)&valh,    g_valh);
    cudaGetSymbolAddress((void**)&offattn, g_offattn);
    cudaGetSymbolAddress((void**)&xb,      g_x);
    cudaGetSymbolAddress((void**)&wp,      g_wp);
    cudaGetSymbolAddress((void**)&bcat,    g_bcat);

    static cudaStream_t s1 = nullptr;
    static cudaEvent_t  e0 = nullptr, ew = nullptr, e1 = nullptr;
    if (s1 == nullptr) {
        cudaStreamCreateWithFlags(&s1, cudaStreamNonBlocking);
        cudaEventCreateWithFlags(&e0, cudaEventDisableTiming);
        cudaEventCreateWithFlags(&ew, cudaEventDisableTiming);
        cudaEventCreateWithFlags(&e1, cudaEventDisableTiming);
    }

    // fork immediately: src_pack depends on nothing
    cudaEventRecord(e0, 0);
    cudaStreamWaitEvent(s1, e0, 0);
    src_pack<<<M_FD/16, 256, 0, s1>>>(source, srcfd);

    // 0) weight pack (B fragments) + bias concat   [main stream]
    {
        WPackArgs a{Wv, Woff, Wattn, Wout, W1, W2, boff, battn};
        wconv_all<<<(376832 + 384 + 255)/256, 256>>>(a, wp, bcat);
    }
    cudaEventRecord(ew, 0);
    cudaStreamWaitEvent(s1, ew, 0);

    // value GEMM on side stream (needs srcfd + wp)
    gemm_fd<1><<<dim3(2, M_FD/64), 128, 0, s1>>>(srcfd, wp + WP_WV, bv, nullptr, mask,
                                                 valh, MV, DIM_, DIM_);
    cudaEventRecord(e1, s1);

    // main stream: LN1 -> proj
    ln_fd_kernel<<<BQ/16, 256>>>(input, ln1_g, ln1_b, pos, qpfd);
    gemm_fd<0><<<dim3(3, BQ/64), 128>>>(qpfd, wp + WP_PROJ, bcat, nullptr, nullptr,
                                        offattn, BQ, 384, DIM_);

    // join, then sampler
    cudaStreamWaitEvent(0, e1, 0);
    sample_kernel<<<BQ, 128>>>(valh, offattn, refp, out_loc, aofd);

    // x = input + attnout @ Wout + bout
    gemm_fd<0><<<dim3(2, BQ/64), 128>>>(aofd, wp + WP_WOUT, bout, input, nullptr,
                                        xb, BQ, DIM_, DIM_);

    // y = LN2(x) -> fragments
    ln_fd_kernel<<<BQ/16, 256>>>(xb, ln2_g, ln2_b, nullptr, ybfd);

    // ffn = relu(y @ W1 + b1) -> fragments
    gemm_fd<2><<<dim3(DFF/128, BQ/64), 128>>>(ybfd, wp + WP_W1, b1, nullptr, nullptr,
                                              ffnfd, BQ, DFF, DIM_);

    // out_x = x + ffn @ W2 + b2
    gemm_fd<0><<<dim3(2, BQ/64), 128>>>(ffnfd, wp + WP_W2, b2, xb, nullptr,
                                        out_x, BQ, DIM_, DFF);
}